// round 14
// baseline (speedup 1.0000x reference)
#include <cuda_runtime.h>
#include <cuda_bf16.h>
#include <cstdint>
#include <cstddef>

static constexpr int kS = 2048, kB = 2, kE = 1024, kH = 16, kHD = 64;
static constexpr int kF = 4096, kL = 4, kV = 32000;
static constexpr int kM = kB * kS;     // 4096
static constexpr int k3E = 3 * kE;     // 3072

// ---------------- scratch (no allocs allowed) ----------------
__device__ float g_h  [(size_t)kM * kE];
__device__ float g_t  [(size_t)kM * kE];
__device__ __nv_bfloat16 g_qkvP [2 * (size_t)kM * k3E];
__device__ __nv_bfloat16 g_hP   [2 * (size_t)kM * kE];
__device__ __nv_bfloat16 g_attnP[2 * (size_t)kM * kE];
__device__ __nv_bfloat16 g_ffP  [2 * (size_t)kM * kF];
__device__ __nv_bfloat16 g_wKQV [(size_t)kL * 2 * k3E * kE];
__device__ __nv_bfloat16 g_wWO  [(size_t)kL * 2 * kE  * kE];
__device__ __nv_bfloat16 g_wUp  [(size_t)kL * 2 * kF  * kE];
__device__ __nv_bfloat16 g_wDn  [(size_t)kL * 2 * kE  * kF];
__device__ __nv_bfloat16 g_wWE  [2 * (size_t)kV * kE];
__device__ int g_is64;

// ---------------- helpers (baseline PTX only) ----------------
__device__ __forceinline__ uint32_t smem_u32(const void* p) {
  uint32_t a;
  asm("{ .reg .u64 t; cvta.to.shared.u64 t, %1; cvt.u32.u64 %0, t; }" : "=r"(a) : "l"(p));
  return a;
}
#define CP_ASYNC16(d, s) \
  asm volatile("cp.async.cg.shared.global [%0], [%1], 16;" :: "r"(d), "l"(s) : "memory")
#define CP_COMMIT() asm volatile("cp.async.commit_group;" ::: "memory")
#define LDSM4(r0, r1, r2, r3, a) \
  asm volatile("ldmatrix.sync.aligned.m8n8.x4.shared.b16 {%0,%1,%2,%3},[%4];" \
               : "=r"(r0), "=r"(r1), "=r"(r2), "=r"(r3) : "r"(a))
#define MMA16816(c, a0, a1, a2, a3, b0, b1) \
  asm volatile("mma.sync.aligned.m16n8k16.row.col.f32.bf16.bf16.f32 " \
               "{%0,%1,%2,%3},{%4,%5,%6,%7},{%8,%9},{%0,%1,%2,%3};" \
               : "+f"((c)[0]), "+f"((c)[1]), "+f"((c)[2]), "+f"((c)[3]) \
               : "r"(a0), "r"(a1), "r"(a2), "r"(a3), "r"(b0), "r"(b1))

__device__ __forceinline__ void split2(float v, __nv_bfloat16& h, __nv_bfloat16& l) {
  h = __float2bfloat16(v);
  l = __float2bfloat16(v - __bfloat162float(h));
}
__device__ __forceinline__ uint32_t packb(__nv_bfloat16 a, __nv_bfloat16 b) {
  return (uint32_t)__bfloat16_as_ushort(a) | ((uint32_t)__bfloat16_as_ushort(b) << 16);
}
__device__ __forceinline__ void packPhl(float x, float y, uint32_t& hw, uint32_t& lw) {
  __nv_bfloat16 xh, xl, yh, yl;
  split2(x, xh, xl); split2(y, yh, yl);
  hw = packb(xh, yh); lw = packb(xl, yl);
}

// ---------------- token dtype detect ----------------
__global__ void detect_x_kernel(const int* __restrict__ xw) {
  if (threadIdx.x == 0 && blockIdx.x == 0) {
    int any = 0;
    for (int i = 1; i < 2048; i += 2) any |= xw[i];
    g_is64 = (any == 0) ? 1 : 0;
  }
}

// ---------------- weight prep ----------------
__global__ __launch_bounds__(256) void wsplitT_kernel(const float* __restrict__ src,
                                                      __nv_bfloat16* __restrict__ dst,
                                                      int Kd, int Nd) {
  __shared__ float t[32][33];
  const size_t lsz = (size_t)Kd * Nd;
  const float* S = src + (size_t)blockIdx.z * lsz;
  __nv_bfloat16* Hh = dst + (size_t)blockIdx.z * 2 * lsz;
  __nv_bfloat16* Ll = Hh + lsz;
  const int k0 = blockIdx.y * 32, n0 = blockIdx.x * 32;
  const int tx = threadIdx.x & 31, ty = threadIdx.x >> 5;
#pragma unroll
  for (int i = 0; i < 32; i += 8)
    t[ty + i][tx] = S[(size_t)(k0 + ty + i) * Nd + n0 + tx];
  __syncthreads();
#pragma unroll
  for (int i = 0; i < 32; i += 8) {
    float v = t[tx][ty + i];
    __nv_bfloat16 h, l; split2(v, h, l);
    size_t o = (size_t)(n0 + ty + i) * Kd + k0 + tx;
    Hh[o] = h; Ll[o] = l;
  }
}
__global__ __launch_bounds__(256) void wsplit_kernel(const float* __restrict__ s,
                                                     __nv_bfloat16* __restrict__ d, size_t n) {
  size_t i = ((size_t)blockIdx.x * 256 + threadIdx.x) * 4;
  if (i >= n) return;
  float4 v = *(const float4*)(s + i);
  __nv_bfloat16 h0,h1,h2,h3,l0,l1,l2,l3;
  split2(v.x,h0,l0); split2(v.y,h1,l1); split2(v.z,h2,l2); split2(v.w,h3,l3);
  uint2 hp; hp.x = packb(h0,h1); hp.y = packb(h2,h3);
  uint2 lp; lp.x = packb(l0,l1); lp.y = packb(l2,l3);
  *(uint2*)(d + i) = hp;
  *(uint2*)(d + n + i) = lp;
}

// ---------------- embedding (fp32 + planes) ----------------
__global__ __launch_bounds__(256) void embed_kernel(const void* __restrict__ x,
                                                    const float* __restrict__ we,
                                                    const float* __restrict__ pe) {
  const int row = blockIdx.x;
  const int s = row & (kS - 1);
  const long long tok = g_is64 ? ((const long long*)x)[row] : (long long)((const int*)x)[row];
  const int c = threadIdx.x * 4;
  float4 wv = *(const float4*)(we + (size_t)tok * kE + c);
  float4 pv = *(const float4*)(pe + (size_t)s * kE + c);
  float4 o;
  o.x = wv.x + pv.x; o.y = wv.y + pv.y; o.z = wv.z + pv.z; o.w = wv.w + pv.w;
  const size_t off = (size_t)row * kE + c;
  *(float4*)(g_h + off) = o;
  __nv_bfloat16 h0,h1,h2,h3,l0,l1,l2,l3;
  split2(o.x,h0,l0); split2(o.y,h1,l1); split2(o.z,h2,l2); split2(o.w,h3,l3);
  uint2 hp; hp.x = packb(h0,h1); hp.y = packb(h2,h3);
  uint2 lp; lp.x = packb(l0,l1); lp.y = packb(l2,l3);
  *(uint2*)(g_hP + off) = hp;
  *(uint2*)(g_hP + (size_t)kM * kE + off) = lp;
}

// ---------------- warp-MMA GEMM (bf16x2-split, 3-term, fp32 acc) ----------------
// 128x128 CTA tile, 8 warps (2m x 4n), K-chunk 32, 3-stage cp.async, 2 CTAs/SM.
// Stage (32KB): A 128 rows x 128B [Ah 64B | Al 64B], B same at +16KB.
// Row swizzle: 16B chunk c (0..7) stored at (c ^ (r&7)).
static constexpr int SMEM_MM = 3 * 32768;

__device__ __forceinline__ void issue_chunk(uint32_t sb, int stage,
                                            const __nv_bfloat16* __restrict__ Ah,
                                            const __nv_bfloat16* __restrict__ Al,
                                            const __nv_bfloat16* __restrict__ Bh,
                                            const __nv_bfloat16* __restrict__ Bl,
                                            int row0, int col0, int k0, int K, int tid) {
#pragma unroll
  for (int i = 0; i < 8; i++) {
    int g = tid + i * 256;          // 0..2047
    int pl = g >> 10;               // 0:A 1:B
    int j = g & 1023;
    int r = j >> 3, c = j & 7;      // row 0..127, 16B chunk 0..7
    const __nv_bfloat16* s;
    if (pl == 0) s = (c < 4 ? Ah + (size_t)(row0 + r) * K + k0 + c * 8
                            : Al + (size_t)(row0 + r) * K + k0 + (c - 4) * 8);
    else         s = (c < 4 ? Bh + (size_t)(col0 + r) * K + k0 + c * 8
                            : Bl + (size_t)(col0 + r) * K + k0 + (c - 4) * 8);
    uint32_t d = sb + stage * 32768 + pl * 16384 + r * 128 + ((c ^ (r & 7)) * 16);
    CP_ASYNC16(d, s);
  }
  CP_COMMIT();
}

template<int EPI, int OUTF, int OUTP>
__global__ __launch_bounds__(256, 2) void mm_gemm(const __nv_bfloat16* __restrict__ Ap,
                                                  const __nv_bfloat16* __restrict__ Bp,
                                                  const float* __restrict__ bias,
                                                  float* __restrict__ C,
                                                  __nv_bfloat16* __restrict__ Cp,
                                                  int M, int N, int K) {
  extern __shared__ char smem[];
  const uint32_t sb = smem_u32(smem);
  const int tid = threadIdx.x, wid = tid >> 5, lane = tid & 31;
  const int row0 = blockIdx.y * 128, col0 = blockIdx.x * 128;
  const size_t PA = (size_t)M * K, PB = (size_t)N * K;
  const __nv_bfloat16 *Ah = Ap, *Al = Ap + PA, *Bh = Bp, *Bl = Bp + PB;
  const int nc = K >> 5;   // chunks of 32

  const int wm = (wid >> 2) * 64, wn = (wid & 3) * 32;
  const int rowa = wm + (lane & 15);
  const int hiA  = lane >> 4;
  const int rowb = wn + (lane & 7) + ((lane >> 4) << 3);
  const int hiB  = (lane >> 3) & 1;

  float acc[4][4][4];
#pragma unroll
  for (int a = 0; a < 4; a++)
#pragma unroll
    for (int b = 0; b < 4; b++)
#pragma unroll
      for (int c = 0; c < 4; c++) acc[a][b][c] = 0.f;

  issue_chunk(sb, 0, Ah, Al, Bh, Bl, row0, col0, 0, K, tid);
  issue_chunk(sb, 1, Ah, Al, Bh, Bl, row0, col0, 32, K, tid);

  for (int ch = 0; ch < nc; ch++) {
    if (ch + 2 < nc) {
      issue_chunk(sb, (ch + 2) % 3, Ah, Al, Bh, Bl, row0, col0, (ch + 2) << 5, K, tid);
      asm volatile("cp.async.wait_group 2;" ::: "memory");
    } else if (ch + 1 < nc) {
      asm volatile("cp.async.wait_group 1;" ::: "memory");
    } else {
      asm volatile("cp.async.wait_group 0;" ::: "memory");
    }
    __syncthreads();

    const uint32_t base = sb + (ch % 3) * 32768;
#pragma unroll
    for (int ks = 0; ks < 2; ks++) {
      uint32_t aH[4][4], aL[4][4];
#pragma unroll
      for (int mf = 0; mf < 4; mf++) {
        const int row = rowa + mf * 16;
        const uint32_t rbase = base + row * 128;
        const int ch_hi = ks * 2 + hiA;
        LDSM4(aH[mf][0], aH[mf][1], aH[mf][2], aH[mf][3],
              rbase + ((ch_hi ^ (row & 7)) << 4));
        LDSM4(aL[mf][0], aL[mf][1], aL[mf][2], aL[mf][3],
              rbase + (((4 + ch_hi) ^ (row & 7)) << 4));
      }
      uint32_t bH[4][2], bL[4][2];
#pragma unroll
      for (int nf2 = 0; nf2 < 2; nf2++) {
        const int row = rowb + nf2 * 16;
        const uint32_t rbase = base + 16384 + row * 128;
        const int ch_hi = ks * 2 + hiB;
        uint32_t r0, r1, r2, r3;
        LDSM4(r0, r1, r2, r3, rbase + ((ch_hi ^ (row & 7)) << 4));
        bH[nf2 * 2][0] = r0; bH[nf2 * 2][1] = r1;
        bH[nf2 * 2 + 1][0] = r2; bH[nf2 * 2 + 1][1] = r3;
        LDSM4(r0, r1, r2, r3, rbase + (((4 + ch_hi) ^ (row & 7)) << 4));
        bL[nf2 * 2][0] = r0; bL[nf2 * 2][1] = r1;
        bL[nf2 * 2 + 1][0] = r2; bL[nf2 * 2 + 1][1] = r3;
      }
#pragma unroll
      for (int mf = 0; mf < 4; mf++)
#pragma unroll
        for (int nf = 0; nf < 4; nf++) {
          MMA16816(acc[mf][nf], aH[mf][0], aH[mf][1], aH[mf][2], aH[mf][3],
                   bH[nf][0], bH[nf][1]);
          MMA16816(acc[mf][nf], aH[mf][0], aH[mf][1], aH[mf][2], aH[mf][3],
                   bL[nf][0], bL[nf][1]);
          MMA16816(acc[mf][nf], aL[mf][0], aL[mf][1], aL[mf][2], aL[mf][3],
                   bH[nf][0], bH[nf][1]);
        }
    }
    __syncthreads();
  }

  const int er = row0 + wm + (lane >> 2);
  const int ec = col0 + wn + (lane & 3) * 2;
#pragma unroll
  for (int mf = 0; mf < 4; mf++) {
#pragma unroll
    for (int nf = 0; nf < 4; nf++) {
      const int cc = ec + nf * 8;
      float b0 = 0.f, b1 = 0.f;
      if (EPI >= 1) { b0 = bias[cc]; b1 = bias[cc + 1]; }
#pragma unroll
      for (int half = 0; half < 2; half++) {
        const int r = er + mf * 16 + half * 8;
        float v0 = acc[mf][nf][half * 2 + 0] + b0;
        float v1 = acc[mf][nf][half * 2 + 1] + b1;
        if (EPI == 2) { v0 = fmaxf(v0, 0.f); v1 = fmaxf(v1, 0.f); }
        const size_t go = (size_t)r * N + cc;
        if (OUTF) {
          float2 o; o.x = v0; o.y = v1;
          *(float2*)(C + go) = o;
        }
        if (OUTP) {
          uint32_t hw, lw;
          packPhl(v0, v1, hw, lw);
          *(uint32_t*)(Cp + go) = hw;
          *(uint32_t*)(Cp + (size_t)M * N + go) = lw;
        }
      }
    }
  }
}

// ---------------- tensor-core causal flash attention ----------------
__global__ __launch_bounds__(256) void attn_mma_kernel(const __nv_bfloat16* __restrict__ qkvP,
                                                       __nv_bfloat16* __restrict__ outP) {
  extern __shared__ char sm[];
  const uint32_t sb = smem_u32(sm);
  const int qt = gridDim.x - 1 - blockIdx.x;
  const int h = blockIdx.y, b = blockIdx.z;
  const int tid = threadIdx.x, w = tid >> 5, lane = tid & 31;
  const size_t rowb = (size_t)b * kS;
  const int hoff = h * 192;
  const size_t PL3 = (size_t)kM * k3E;
  const size_t PLE = (size_t)kM * kE;

#pragma unroll
  for (int it = 0; it < 4; it++) {
    int idx = tid + it * 256;
    int r = idx >> 3, c16 = idx & 7;
    size_t g = (rowb + qt * 128 + r) * k3E + hoff + 64 + c16 * 8;
    uint4 vh = *(const uint4*)(qkvP + g);
    uint4 vl = *(const uint4*)(qkvP + PL3 + g);
    uint32_t d = r * 128 + (((c16 ^ (r & 7))) * 16);
    *(uint4*)(sm + d) = vh;
    *(uint4*)(sm + 16384 + d) = vl;
  }

  const int rw = w * 16;
  const int rA = rw + (lane & 15);
  const int hiA = lane >> 4;
  const int rB = (lane & 7) + ((lane >> 4) << 3);
  const int hiB = (lane >> 3) & 1;
  const int rr = lane >> 2;
  const int cc2 = (lane & 3) * 2;

  float oacc[8][4];
#pragma unroll
  for (int nf = 0; nf < 8; nf++)
#pragma unroll
    for (int j = 0; j < 4; j++) oacc[nf][j] = 0.f;
  float m0 = -1e30f, m1 = -1e30f, l0 = 0.f, l1 = 0.f;

  const int grow0 = qt * 128 + rw + rr;
  const int nkt = 2 * qt + 2;

  for (int kt = 0; kt < nkt; kt++) {
    __syncthreads();
#pragma unroll
    for (int it = 0; it < 2; it++) {
      int idx = tid + it * 256;
      int r = idx >> 3, c16 = idx & 7;
      size_t g = (rowb + kt * 64 + r) * k3E + hoff + c16 * 8;
      uint4 vh = *(const uint4*)(qkvP + g);
      uint4 vl = *(const uint4*)(qkvP + PL3 + g);
      uint32_t d = r * 128 + ((c16 ^ (r & 7)) * 16);
      *(uint4*)(sm + 32768 + d) = vh;
      *(uint4*)(sm + 40960 + d) = vl;
    }
#pragma unroll
    for (int it = 0; it < 2; it++) {
      int idx = tid + it * 256;
      int kp = idx >> 3, d8 = idx & 7;
      size_t g = (rowb + kt * 64 + kp) * k3E + hoff + 128 + d8 * 8;
      uint4 vh = *(const uint4*)(qkvP + g);
      uint4 vl = *(const uint4*)(qkvP + PL3 + g);
      const unsigned short* ph = (const unsigned short*)&vh;
      const unsigned short* pl = (const unsigned short*)&vl;
#pragma unroll
      for (int j = 0; j < 8; j++) {
        uint32_t off = (d8 * 8 + j) * 128 + (((kp >> 3) ^ j) * 16) + (kp & 7) * 2;
        *(unsigned short*)(sm + 49152 + off) = ph[j];
        *(unsigned short*)(sm + 57344 + off) = pl[j];
      }
    }
    __syncthreads();

    float sacc[8][4];
#pragma unroll
    for (int nf = 0; nf < 8; nf++)
#pragma unroll
      for (int j = 0; j < 4; j++) sacc[nf][j] = 0.f;

#pragma unroll
    for (int ks = 0; ks < 4; ks++) {
      uint32_t qh[4], ql[4];
      const uint32_t ad = sb + rA * 128 + (((ks * 2 + hiA) ^ (rA & 7)) << 4);
      LDSM4(qh[0], qh[1], qh[2], qh[3], ad);
      LDSM4(ql[0], ql[1], ql[2], ql[3], ad + 16384);
#pragma unroll
      for (int nf16 = 0; nf16 < 4; nf16++) {
        const int row = nf16 * 16 + rB;
        const uint32_t bd = sb + 32768 + row * 128 + (((ks * 2 + hiB) ^ (row & 7)) << 4);
        uint32_t b0, b1, b2, b3, c0, c1, c2, c3;
        LDSM4(b0, b1, b2, b3, bd);
        LDSM4(c0, c1, c2, c3, bd + 8192);
        MMA16816(sacc[nf16 * 2],     qh[0], qh[1], qh[2], qh[3], b0, b1);
        MMA16816(sacc[nf16 * 2],     qh[0], qh[1], qh[2], qh[3], c0, c1);
        MMA16816(sacc[nf16 * 2],     ql[0], ql[1], ql[2], ql[3], b0, b1);
        MMA16816(sacc[nf16 * 2 + 1], qh[0], qh[1], qh[2], qh[3], b2, b3);
        MMA16816(sacc[nf16 * 2 + 1], qh[0], qh[1], qh[2], qh[3], c2, c3);
        MMA16816(sacc[nf16 * 2 + 1], ql[0], ql[1], ql[2], ql[3], b2, b3);
      }
    }

    const bool diag = (kt >= 2 * qt);
    float mx0 = -1e30f, mx1 = -1e30f;
#pragma unroll
    for (int nf = 0; nf < 8; nf++) {
      float s0 = sacc[nf][0] * 0.125f, s1 = sacc[nf][1] * 0.125f;
      float s2 = sacc[nf][2] * 0.125f, s3 = sacc[nf][3] * 0.125f;
      if (diag) {
        const int c0 = kt * 64 + nf * 8 + cc2;
        if (c0     > grow0)     s0 = -1e30f;
        if (c0 + 1 > grow0)     s1 = -1e30f;
        if (c0     > grow0 + 8) s2 = -1e30f;
        if (c0 + 1 > grow0 + 8) s3 = -1e30f;
      }
      sacc[nf][0] = s0; sacc[nf][1] = s1; sacc[nf][2] = s2; sacc[nf][3] = s3;
      mx0 = fmaxf(mx0, fmaxf(s0, s1));
      mx1 = fmaxf(mx1, fmaxf(s2, s3));
    }
    mx0 = fmaxf(mx0, __shfl_xor_sync(0xffffffffu, mx0, 1));
    mx0 = fmaxf(mx0, __shfl_xor_sync(0xffffffffu, mx0, 2));
    mx1 = fmaxf(mx1, __shfl_xor_sync(0xffffffffu, mx1, 1));
    mx1 = fmaxf(mx1, __shfl_xor_sync(0xffffffffu, mx1, 2));
    const float m0n = fmaxf(m0, mx0), m1n = fmaxf(m1, mx1);
    const float corr0 = __expf(m0 - m0n), corr1 = __expf(m1 - m1n);
    float rs0 = 0.f, rs1 = 0.f;
#pragma unroll
    for (int nf = 0; nf < 8; nf++) {
      float p0 = __expf(sacc[nf][0] - m0n);
      float p1 = __expf(sacc[nf][1] - m0n);
      float p2 = __expf(sacc[nf][2] - m1n);
      float p3 = __expf(sacc[nf][3] - m1n);
      sacc[nf][0] = p0; sacc[nf][1] = p1; sacc[nf][2] = p2; sacc[nf][3] = p3;
      rs0 += p0 + p1; rs1 += p2 + p3;
    }
    rs0 += __shfl_xor_sync(0xffffffffu, rs0, 1);
    rs0 += __shfl_xor_sync(0xffffffffu, rs0, 2);
    rs1 += __shfl_xor_sync(0xffffffffu, rs1, 1);
    rs1 += __shfl_xor_sync(0xffffffffu, rs1, 2);
    m0 = m0n; m1 = m1n;
    l0 = l0 * corr0 + rs0;
    l1 = l1 * corr1 + rs1;
#pragma unroll
    for (int nf = 0; nf < 8; nf++) {
      oacc[nf][0] *= corr0; oacc[nf][1] *= corr0;
      oacc[nf][2] *= corr1; oacc[nf][3] *= corr1;
    }

#pragma unroll
    for (int kg = 0; kg < 4; kg++) {
      uint32_t ah[4], al[4];
      packPhl(sacc[2 * kg][0],     sacc[2 * kg][1],     ah[0], al[0]);
      packPhl(sacc[2 * kg][2],     sacc[2 * kg][3],     ah[1], al[1]);
      packPhl(sacc[2 * kg + 1][0], sacc[2 * kg + 1][1], ah[2], al[2]);
      packPhl(sacc[2 * kg + 1][2], sacc[2 * kg + 1][3], ah[3], al[3]);
#pragma unroll
      for (int nf16 = 0; nf16 < 4; nf16++) {
        const int row = nf16 * 16 + rB;
        const uint32_t bd = sb + 49152 + row * 128 + (((kg * 2 + hiB) ^ (row & 7)) << 4);
        uint32_t b0, b1, b2, b3, c0, c1, c2, c3;
        LDSM4(b0, b1, b2, b3, bd);
        LDSM4(c0, c1, c2, c3, bd + 8192);
        MMA16816(oacc[nf16 * 2],     ah[0], ah[1], ah[2], ah[3], b0, b1);
        MMA16816(oacc[nf16 * 2],     ah[0], ah[1], ah[2], ah[3], c0, c1);
        MMA16816(oacc[nf16 * 2],     al[0], al[1], al[2], al[3], b0, b1);
        MMA16816(oacc[nf16 * 2 + 1], ah[0], ah[1], ah[2], ah[3], b2, b3);
        MMA16816(oacc[nf16 * 2 + 1], ah[0], ah[1], ah[2], ah[3], c2, c3);
        MMA16816(oacc[nf16 * 2 + 1], al[0], al[1], al[2], al[3], b2, b3);
      }
    }
  }

  const float inv0 = 1.f / l0, inv1 = 1.f / l1;
#pragma unroll
  for (int nf = 0; nf < 8; nf++) {
    const int d = h * 64 + nf * 8 + cc2;
    const size_t o0 = (rowb + grow0) * kE + d;
    const size_t o1 = (rowb + grow0 + 8) * kE + d;
    uint32_t hw, lw;
    packPhl(oacc[nf][0] * inv0, oacc[nf][1] * inv0, hw, lw);
    *(uint32_t*)(outP + o0) = hw;
    *(uint32_t*)(outP + PLE + o0) = lw;
    packPhl(oacc[nf][2] * inv1, oacc[nf][3] * inv1, hw, lw);
    *(uint32_t*)(outP + o1) = hw;
    *(uint32_t*)(outP + PLE + o1) = lw;
  }
}

// ---------------- LayerNorm + residual (fp32 + planes) ----------------
__global__ __launch_bounds__(256) void ln_add_kernel(const float* __restrict__ x,
                                                     const float* __restrict__ gamma,
                                                     const float* __restrict__ beta,
                                                     float* __restrict__ h,
                                                     __nv_bfloat16* __restrict__ hP) {
  __shared__ float rs[8], rs2[8];
  const int row = blockIdx.x, tid = threadIdx.x;
  const int c = tid * 4;
  const size_t off = (size_t)row * kE + c;
  float4 xv = *(const float4*)(x + off);
  float s = xv.x + xv.y + xv.z + xv.w;
  float s2 = xv.x*xv.x + xv.y*xv.y + xv.z*xv.z + xv.w*xv.w;
#pragma unroll
  for (int o = 16; o; o >>= 1) {
    s  += __shfl_xor_sync(0xffffffffu, s, o);
    s2 += __shfl_xor_sync(0xffffffffu, s2, o);
  }
  if ((tid & 31) == 0) { rs[tid >> 5] = s; rs2[tid >> 5] = s2; }
  __syncthreads();
  float ts = 0.f, ts2 = 0.f;
#pragma unroll
  for (int i = 0; i < 8; i++) { ts += rs[i]; ts2 += rs2[i]; }
  const float mean = ts * (1.f / kE);
  const float var = ts2 * (1.f / kE) - mean * mean;
  const float rstd = rsqrtf(var + 1e-6f);
  float4 hv = *(const float4*)(h + off);
  float4 gv = *(const float4*)(gamma + c);
  float4 bv = *(const float4*)(beta + c);
  float4 o4;
  o4.x = (xv.x - mean) * rstd * gv.x + bv.x + hv.x;
  o4.y = (xv.y - mean) * rstd * gv.y + bv.y + hv.y;
  o4.z = (xv.z - mean) * rstd * gv.z + bv.z + hv.z;
  o4.w = (xv.w - mean) * rstd * gv.w + bv.w + hv.w;
  *(float4*)(h + off) = o4;
  __nv_bfloat16 h0,h1,h2,h3,l0,l1,l2,l3;
  split2(o4.x,h0,l0); split2(o4.y,h1,l1); split2(o4.z,h2,l2); split2(o4.w,h3,l3);
  uint2 hp; hp.x = packb(h0,h1); hp.y = packb(h2,h3);
  uint2 lp; lp.x = packb(l0,l1); lp.y = packb(l2,l3);
  *(uint2*)(hP + off) = hp;
  *(uint2*)(hP + (size_t)kM * kE + off) = lp;
}

// ---------------- launcher ----------------
extern "C" void kernel_launch(void* const* d_in, const int* in_sizes, int n_in,
                              void* d_out, int out_size) {
  (void)in_sizes; (void)n_in; (void)out_size;
  const void*  x   = d_in[0];
  const float* we  = (const float*)d_in[1];
  const float* pe  = (const float*)d_in[2];
  const float* KQV = (const float*)d_in[3];
  const float* WO  = (const float*)d_in[4];
  const float* Wup = (const float*)d_in[5];
  const float* bup = (const float*)d_in[6];
  const float* Wdn = (const float*)d_in[7];
  const float* bdn = (const float*)d_in[8];
  const float* g1  = (const float*)d_in[9];
  const float* b1  = (const float*)d_in[10];
  const float* g2  = (const float*)d_in[11];
  const float* b2  = (const float*)d_in[12];
  const float* ub  = (const float*)d_in[13];
  float* out = (float*)d_out;

  float *h, *tb;
  __nv_bfloat16 *qkvP, *hP, *attnP, *ffP, *wKQV, *wWO, *wUp, *wDn, *wWE;
  cudaGetSymbolAddress((void**)&h,     g_h);
  cudaGetSymbolAddress((void**)&tb,    g_t);
  cudaGetSymbolAddress((void**)&qkvP,  g_qkvP);
  cudaGetSymbolAddress((void**)&hP,    g_hP);
  cudaGetSymbolAddress((void**)&attnP, g_attnP);
  cudaGetSymbolAddress((void**)&ffP,   g_ffP);
  cudaGetSymbolAddress((void**)&wKQV,  g_wKQV);
  cudaGetSymbolAddress((void**)&wWO,   g_wWO);
  cudaGetSymbolAddress((void**)&wUp,   g_wUp);
  cudaGetSymbolAddress((void**)&wDn,   g_wDn);
  cudaGetSymbolAddress((void**)&wWE,   g_wWE);

  cudaFuncSetAttribute(attn_mma_kernel, cudaFuncAttributeMaxDynamicSharedMemorySize, 64 * 1024);
  cudaFuncSetAttribute(mm_gemm<0,0,1>, cudaFuncAttributeMaxDynamicSharedMemorySize, SMEM_MM);
  cudaFuncSetAttribute(mm_gemm<0,1,0>, cudaFuncAttributeMaxDynamicSharedMemorySize, SMEM_MM);
  cudaFuncSetAttribute(mm_gemm<2,0,1>, cudaFuncAttributeMaxDynamicSharedMemorySize, SMEM_MM);
  cudaFuncSetAttribute(mm_gemm<1,1,0>, cudaFuncAttributeMaxDynamicSharedMemorySize, SMEM_MM);

  detect_x_kernel<<<1, 32>>>((const int*)x);
  embed_kernel<<<kM, 256>>>(x, we, pe);

  wsplitT_kernel<<<dim3(k3E/32, kE/32, kL), 256>>>(KQV, wKQV, kE, k3E);
  wsplitT_kernel<<<dim3(kE/32,  kE/32, kL), 256>>>(WO,  wWO,  kE, kE);
  wsplitT_kernel<<<dim3(kF/32,  kE/32, kL), 256>>>(Wup, wUp,  kE, kF);
  wsplitT_kernel<<<dim3(kE/32,  kF/32, kL), 256>>>(Wdn, wDn,  kF, kE);
  wsplit_kernel<<<(unsigned)(((size_t)kV*kE/4 + 255)/256), 256>>>(we, wWE, (size_t)kV*kE);

  for (int l = 0; l < kL; l++) {
    mm_gemm<0,0,1><<<dim3(k3E/128, kM/128), 256, SMEM_MM>>>(
        hP, wKQV + (size_t)l*2*k3E*kE, nullptr, nullptr, qkvP, kM, k3E, kE);
    attn_mma_kernel<<<dim3(kS/128, kH, kB), 256, 64*1024>>>(qkvP, attnP);
    mm_gemm<0,1,0><<<dim3(kE/128, kM/128), 256, SMEM_MM>>>(
        attnP, wWO + (size_t)l*2*kE*kE, nullptr, tb, nullptr, kM, kE, kE);
    ln_add_kernel<<<kM, 256>>>(tb, g1 + l*kE, b1 + l*kE, h, hP);
    mm_gemm<2,0,1><<<dim3(kF/128, kM/128), 256, SMEM_MM>>>(
        hP, wUp + (size_t)l*2*kF*kE, bup + (size_t)l*kF, nullptr, ffP, kM, kF, kE);
    mm_gemm<1,1,0><<<dim3(kE/128, kM/128), 256, SMEM_MM>>>(
        ffP, wDn + (size_t)l*2*kE*kF, bdn + (size_t)l*kE, tb, nullptr, kM, kE, kF);
    ln_add_kernel<<<kM, 256>>>(tb, g2 + l*kE, b2 + l*kE, h, hP);
  }

  mm_gemm<1,1,0><<<dim3(kV/128, kM/128), 256, SMEM_MM>>>(
      hP, wWE, ub, out, nullptr, kM, kV, kE);
}

// round 15
// speedup vs baseline: 1.0241x; 1.0241x over previous
#include <cuda_runtime.h>
#include <cuda_bf16.h>
#include <cstdint>
#include <cstddef>

static constexpr int kS = 2048, kB = 2, kE = 1024, kH = 16, kHD = 64;
static constexpr int kF = 4096, kL = 4, kV = 32000;
static constexpr int kM = kB * kS;     // 4096
static constexpr int k3E = 3 * kE;     // 3072

// ---------------- scratch (no allocs allowed) ----------------
__device__ float g_h  [(size_t)kM * kE];
__device__ float g_t  [(size_t)kM * kE];
__device__ __nv_bfloat16 g_qkvP [2 * (size_t)kM * k3E];
__device__ __nv_bfloat16 g_hP   [2 * (size_t)kM * kE];
__device__ __nv_bfloat16 g_attnP[2 * (size_t)kM * kE];
__device__ __nv_bfloat16 g_ffP  [2 * (size_t)kM * kF];
__device__ __nv_bfloat16 g_wKQV [(size_t)kL * 2 * k3E * kE];
__device__ __nv_bfloat16 g_wWO  [(size_t)kL * 2 * kE  * kE];
__device__ __nv_bfloat16 g_wUp  [(size_t)kL * 2 * kF  * kE];
__device__ __nv_bfloat16 g_wDn  [(size_t)kL * 2 * kE  * kF];
__device__ __nv_bfloat16 g_wWE  [2 * (size_t)kV * kE];
__device__ int g_is64;

// ---------------- helpers (baseline PTX only) ----------------
__device__ __forceinline__ uint32_t smem_u32(const void* p) {
  uint32_t a;
  asm("{ .reg .u64 t; cvta.to.shared.u64 t, %1; cvt.u32.u64 %0, t; }" : "=r"(a) : "l"(p));
  return a;
}
#define CP_ASYNC16(d, s) \
  asm volatile("cp.async.cg.shared.global [%0], [%1], 16;" :: "r"(d), "l"(s) : "memory")
#define CP_COMMIT() asm volatile("cp.async.commit_group;" ::: "memory")
#define LDSM4(r0, r1, r2, r3, a) \
  asm volatile("ldmatrix.sync.aligned.m8n8.x4.shared.b16 {%0,%1,%2,%3},[%4];" \
               : "=r"(r0), "=r"(r1), "=r"(r2), "=r"(r3) : "r"(a))
#define MMA16816(c, a0, a1, a2, a3, b0, b1) \
  asm volatile("mma.sync.aligned.m16n8k16.row.col.f32.bf16.bf16.f32 " \
               "{%0,%1,%2,%3},{%4,%5,%6,%7},{%8,%9},{%0,%1,%2,%3};" \
               : "+f"((c)[0]), "+f"((c)[1]), "+f"((c)[2]), "+f"((c)[3]) \
               : "r"(a0), "r"(a1), "r"(a2), "r"(a3), "r"(b0), "r"(b1))

__device__ __forceinline__ void split2(float v, __nv_bfloat16& h, __nv_bfloat16& l) {
  h = __float2bfloat16(v);
  l = __float2bfloat16(v - __bfloat162float(h));
}
__device__ __forceinline__ uint32_t packb(__nv_bfloat16 a, __nv_bfloat16 b) {
  return (uint32_t)__bfloat16_as_ushort(a) | ((uint32_t)__bfloat16_as_ushort(b) << 16);
}
__device__ __forceinline__ void packPhl(float x, float y, uint32_t& hw, uint32_t& lw) {
  __nv_bfloat16 xh, xl, yh, yl;
  split2(x, xh, xl); split2(y, yh, yl);
  hw = packb(xh, yh); lw = packb(xl, yl);
}

// ---------------- token dtype detect ----------------
__global__ void detect_x_kernel(const int* __restrict__ xw) {
  if (threadIdx.x == 0 && blockIdx.x == 0) {
    int any = 0;
    for (int i = 1; i < 2048; i += 2) any |= xw[i];
    g_is64 = (any == 0) ? 1 : 0;
  }
}

// ---------------- weight prep ----------------
__global__ __launch_bounds__(256) void wsplitT_kernel(const float* __restrict__ src,
                                                      __nv_bfloat16* __restrict__ dst,
                                                      int Kd, int Nd) {
  __shared__ float t[32][33];
  const size_t lsz = (size_t)Kd * Nd;
  const float* S = src + (size_t)blockIdx.z * lsz;
  __nv_bfloat16* Hh = dst + (size_t)blockIdx.z * 2 * lsz;
  __nv_bfloat16* Ll = Hh + lsz;
  const int k0 = blockIdx.y * 32, n0 = blockIdx.x * 32;
  const int tx = threadIdx.x & 31, ty = threadIdx.x >> 5;
#pragma unroll
  for (int i = 0; i < 32; i += 8)
    t[ty + i][tx] = S[(size_t)(k0 + ty + i) * Nd + n0 + tx];
  __syncthreads();
#pragma unroll
  for (int i = 0; i < 32; i += 8) {
    float v = t[tx][ty + i];
    __nv_bfloat16 h, l; split2(v, h, l);
    size_t o = (size_t)(n0 + ty + i) * Kd + k0 + tx;
    Hh[o] = h; Ll[o] = l;
  }
}
__global__ __launch_bounds__(256) void wsplit_kernel(const float* __restrict__ s,
                                                     __nv_bfloat16* __restrict__ d, size_t n) {
  size_t i = ((size_t)blockIdx.x * 256 + threadIdx.x) * 4;
  if (i >= n) return;
  float4 v = *(const float4*)(s + i);
  __nv_bfloat16 h0,h1,h2,h3,l0,l1,l2,l3;
  split2(v.x,h0,l0); split2(v.y,h1,l1); split2(v.z,h2,l2); split2(v.w,h3,l3);
  uint2 hp; hp.x = packb(h0,h1); hp.y = packb(h2,h3);
  uint2 lp; lp.x = packb(l0,l1); lp.y = packb(l2,l3);
  *(uint2*)(d + i) = hp;
  *(uint2*)(d + n + i) = lp;
}

// ---------------- embedding (fp32 + planes) ----------------
__global__ __launch_bounds__(256) void embed_kernel(const void* __restrict__ x,
                                                    const float* __restrict__ we,
                                                    const float* __restrict__ pe) {
  const int row = blockIdx.x;
  const int s = row & (kS - 1);
  const long long tok = g_is64 ? ((const long long*)x)[row] : (long long)((const int*)x)[row];
  const int c = threadIdx.x * 4;
  float4 wv = *(const float4*)(we + (size_t)tok * kE + c);
  float4 pv = *(const float4*)(pe + (size_t)s * kE + c);
  float4 o;
  o.x = wv.x + pv.x; o.y = wv.y + pv.y; o.z = wv.z + pv.z; o.w = wv.w + pv.w;
  const size_t off = (size_t)row * kE + c;
  *(float4*)(g_h + off) = o;
  __nv_bfloat16 h0,h1,h2,h3,l0,l1,l2,l3;
  split2(o.x,h0,l0); split2(o.y,h1,l1); split2(o.z,h2,l2); split2(o.w,h3,l3);
  uint2 hp; hp.x = packb(h0,h1); hp.y = packb(h2,h3);
  uint2 lp; lp.x = packb(l0,l1); lp.y = packb(l2,l3);
  *(uint2*)(g_hP + off) = hp;
  *(uint2*)(g_hP + (size_t)kM * kE + off) = lp;
}

// ---------------- warp-MMA GEMM (bf16x2-split, 3-term, fp32 acc) ----------------
// 128x128 CTA tile, 8 warps (2m x 4n), warp tile 64x32, K-chunk 64, cp.async x2.
// Grid: blockIdx.x = M-tile (FAST — keeps B tiles L2-resident when N*K > L2),
//       blockIdx.y = N-tile.
static constexpr int SMEM_MM = 2 * 65536;

__device__ __forceinline__ void issue_chunk(uint32_t sb, int b,
                                            const __nv_bfloat16* __restrict__ Ah,
                                            const __nv_bfloat16* __restrict__ Al,
                                            const __nv_bfloat16* __restrict__ Bh,
                                            const __nv_bfloat16* __restrict__ Bl,
                                            int row0, int col0, int k0, int K, int tid) {
#pragma unroll
  for (int i = 0; i < 16; i++) {
    int g = tid + i * 256;
    int pl = g >> 10;
    int j = g & 1023;
    int r = j >> 3, c = j & 7;
    const __nv_bfloat16* s;
    if (pl == 0)      s = Ah + (size_t)(row0 + r) * K + k0 + c * 8;
    else if (pl == 1) s = Al + (size_t)(row0 + r) * K + k0 + c * 8;
    else if (pl == 2) s = Bh + (size_t)(col0 + r) * K + k0 + c * 8;
    else              s = Bl + (size_t)(col0 + r) * K + k0 + c * 8;
    uint32_t d = sb + b * 65536 + pl * 16384 + r * 128 + ((c ^ (r & 7)) * 16);
    CP_ASYNC16(d, s);
  }
  CP_COMMIT();
}

template<int EPI, int OUTF, int OUTP>
__global__ __launch_bounds__(256) void mm_gemm(const __nv_bfloat16* __restrict__ Ap,
                                               const __nv_bfloat16* __restrict__ Bp,
                                               const float* __restrict__ bias,
                                               float* __restrict__ C,
                                               __nv_bfloat16* __restrict__ Cp,
                                               int M, int N, int K) {
  extern __shared__ char smem[];
  const uint32_t sb = smem_u32(smem);
  const int tid = threadIdx.x, wid = tid >> 5, lane = tid & 31;
  const int row0 = blockIdx.x * 128, col0 = blockIdx.y * 128;   // M fast
  const size_t PA = (size_t)M * K, PB = (size_t)N * K;
  const __nv_bfloat16 *Ah = Ap, *Al = Ap + PA, *Bh = Bp, *Bl = Bp + PB;
  const int nc = K >> 6;

  const int wm = (wid >> 2) * 64, wn = (wid & 3) * 32;
  const int rowa = wm + (lane & 15);
  const int hiA  = lane >> 4;
  const int rowb = wn + (lane & 7) + ((lane >> 4) << 3);
  const int hiB  = (lane >> 3) & 1;

  float acc[4][4][4];
#pragma unroll
  for (int a = 0; a < 4; a++)
#pragma unroll
    for (int b = 0; b < 4; b++)
#pragma unroll
      for (int c = 0; c < 4; c++) acc[a][b][c] = 0.f;

  issue_chunk(sb, 0, Ah, Al, Bh, Bl, row0, col0, 0, K, tid);

  for (int ch = 0; ch < nc; ch++) {
    if (ch + 1 < nc) {
      issue_chunk(sb, (ch + 1) & 1, Ah, Al, Bh, Bl, row0, col0, (ch + 1) << 6, K, tid);
      asm volatile("cp.async.wait_group 1;" ::: "memory");
    } else {
      asm volatile("cp.async.wait_group 0;" ::: "memory");
    }
    __syncthreads();

    const uint32_t base = sb + (ch & 1) * 65536;
#pragma unroll
    for (int ks = 0; ks < 4; ks++) {
      uint32_t aH[4][4], aL[4][4];
#pragma unroll
      for (int mf = 0; mf < 4; mf++) {
        const int row = rowa + mf * 16;
        const uint32_t ad = base + row * 128 + (((ks * 2 + hiA) ^ (row & 7)) << 4);
        LDSM4(aH[mf][0], aH[mf][1], aH[mf][2], aH[mf][3], ad);
        LDSM4(aL[mf][0], aL[mf][1], aL[mf][2], aL[mf][3], ad + 16384);
      }
      uint32_t bH[4][2], bL[4][2];
#pragma unroll
      for (int nf2 = 0; nf2 < 2; nf2++) {
        const int row = rowb + nf2 * 16;
        const uint32_t bd = base + 32768 + row * 128 + (((ks * 2 + hiB) ^ (row & 7)) << 4);
        uint32_t r0, r1, r2, r3;
        LDSM4(r0, r1, r2, r3, bd);
        bH[nf2 * 2][0] = r0; bH[nf2 * 2][1] = r1;
        bH[nf2 * 2 + 1][0] = r2; bH[nf2 * 2 + 1][1] = r3;
        LDSM4(r0, r1, r2, r3, bd + 16384);
        bL[nf2 * 2][0] = r0; bL[nf2 * 2][1] = r1;
        bL[nf2 * 2 + 1][0] = r2; bL[nf2 * 2 + 1][1] = r3;
      }
#pragma unroll
      for (int mf = 0; mf < 4; mf++)
#pragma unroll
        for (int nf = 0; nf < 4; nf++) {
          MMA16816(acc[mf][nf], aH[mf][0], aH[mf][1], aH[mf][2], aH[mf][3],
                   bH[nf][0], bH[nf][1]);
          MMA16816(acc[mf][nf], aH[mf][0], aH[mf][1], aH[mf][2], aH[mf][3],
                   bL[nf][0], bL[nf][1]);
          MMA16816(acc[mf][nf], aL[mf][0], aL[mf][1], aL[mf][2], aL[mf][3],
                   bH[nf][0], bH[nf][1]);
        }
    }
    __syncthreads();
  }

  const int er = row0 + wm + (lane >> 2);
  const int ec = col0 + wn + (lane & 3) * 2;
#pragma unroll
  for (int mf = 0; mf < 4; mf++) {
#pragma unroll
    for (int nf = 0; nf < 4; nf++) {
      const int cc = ec + nf * 8;
      float b0 = 0.f, b1 = 0.f;
      if (EPI >= 1) { b0 = bias[cc]; b1 = bias[cc + 1]; }
#pragma unroll
      for (int half = 0; half < 2; half++) {
        const int r = er + mf * 16 + half * 8;
        float v0 = acc[mf][nf][half * 2 + 0] + b0;
        float v1 = acc[mf][nf][half * 2 + 1] + b1;
        if (EPI == 2) { v0 = fmaxf(v0, 0.f); v1 = fmaxf(v1, 0.f); }
        const size_t go = (size_t)r * N + cc;
        if (OUTF) {
          float2 o; o.x = v0; o.y = v1;
          *(float2*)(C + go) = o;
        }
        if (OUTP) {
          uint32_t hw, lw;
          packPhl(v0, v1, hw, lw);
          *(uint32_t*)(Cp + go) = hw;
          *(uint32_t*)(Cp + (size_t)M * N + go) = lw;
        }
      }
    }
  }
}

// ---------------- tensor-core causal flash attention ----------------
__global__ __launch_bounds__(256) void attn_mma_kernel(const __nv_bfloat16* __restrict__ qkvP,
                                                       __nv_bfloat16* __restrict__ outP) {
  extern __shared__ char sm[];
  const uint32_t sb = smem_u32(sm);
  const int qt = gridDim.x - 1 - blockIdx.x;
  const int h = blockIdx.y, b = blockIdx.z;
  const int tid = threadIdx.x, w = tid >> 5, lane = tid & 31;
  const size_t rowb = (size_t)b * kS;
  const int hoff = h * 192;
  const size_t PL3 = (size_t)kM * k3E;
  const size_t PLE = (size_t)kM * kE;

#pragma unroll
  for (int it = 0; it < 4; it++) {
    int idx = tid + it * 256;
    int r = idx >> 3, c16 = idx & 7;
    size_t g = (rowb + qt * 128 + r) * k3E + hoff + 64 + c16 * 8;
    uint4 vh = *(const uint4*)(qkvP + g);
    uint4 vl = *(const uint4*)(qkvP + PL3 + g);
    uint32_t d = r * 128 + (((c16 ^ (r & 7))) * 16);
    *(uint4*)(sm + d) = vh;
    *(uint4*)(sm + 16384 + d) = vl;
  }

  const int rw = w * 16;
  const int rA = rw + (lane & 15);
  const int hiA = lane >> 4;
  const int rB = (lane & 7) + ((lane >> 4) << 3);
  const int hiB = (lane >> 3) & 1;
  const int rr = lane >> 2;
  const int cc2 = (lane & 3) * 2;

  float oacc[8][4];
#pragma unroll
  for (int nf = 0; nf < 8; nf++)
#pragma unroll
    for (int j = 0; j < 4; j++) oacc[nf][j] = 0.f;
  float m0 = -1e30f, m1 = -1e30f, l0 = 0.f, l1 = 0.f;

  const int grow0 = qt * 128 + rw + rr;
  const int nkt = 2 * qt + 2;

  for (int kt = 0; kt < nkt; kt++) {
    __syncthreads();
#pragma unroll
    for (int it = 0; it < 2; it++) {
      int idx = tid + it * 256;
      int r = idx >> 3, c16 = idx & 7;
      size_t g = (rowb + kt * 64 + r) * k3E + hoff + c16 * 8;
      uint4 vh = *(const uint4*)(qkvP + g);
      uint4 vl = *(const uint4*)(qkvP + PL3 + g);
      uint32_t d = r * 128 + ((c16 ^ (r & 7)) * 16);
      *(uint4*)(sm + 32768 + d) = vh;
      *(uint4*)(sm + 40960 + d) = vl;
    }
#pragma unroll
    for (int it = 0; it < 2; it++) {
      int idx = tid + it * 256;
      int kp = idx >> 3, d8 = idx & 7;
      size_t g = (rowb + kt * 64 + kp) * k3E + hoff + 128 + d8 * 8;
      uint4 vh = *(const uint4*)(qkvP + g);
      uint4 vl = *(const uint4*)(qkvP + PL3 + g);
      const unsigned short* ph = (const unsigned short*)&vh;
      const unsigned short* pl = (const unsigned short*)&vl;
#pragma unroll
      for (int j = 0; j < 8; j++) {
        uint32_t off = (d8 * 8 + j) * 128 + (((kp >> 3) ^ j) * 16) + (kp & 7) * 2;
        *(unsigned short*)(sm + 49152 + off) = ph[j];
        *(unsigned short*)(sm + 57344 + off) = pl[j];
      }
    }
    __syncthreads();

    float sacc[8][4];
#pragma unroll
    for (int nf = 0; nf < 8; nf++)
#pragma unroll
      for (int j = 0; j < 4; j++) sacc[nf][j] = 0.f;

#pragma unroll
    for (int ks = 0; ks < 4; ks++) {
      uint32_t qh[4], ql[4];
      const uint32_t ad = sb + rA * 128 + (((ks * 2 + hiA) ^ (rA & 7)) << 4);
      LDSM4(qh[0], qh[1], qh[2], qh[3], ad);
      LDSM4(ql[0], ql[1], ql[2], ql[3], ad + 16384);
#pragma unroll
      for (int nf16 = 0; nf16 < 4; nf16++) {
        const int row = nf16 * 16 + rB;
        const uint32_t bd = sb + 32768 + row * 128 + (((ks * 2 + hiB) ^ (row & 7)) << 4);
        uint32_t b0, b1, b2, b3, c0, c1, c2, c3;
        LDSM4(b0, b1, b2, b3, bd);
        LDSM4(c0, c1, c2, c3, bd + 8192);
        MMA16816(sacc[nf16 * 2],     qh[0], qh[1], qh[2], qh[3], b0, b1);
        MMA16816(sacc[nf16 * 2],     qh[0], qh[1], qh[2], qh[3], c0, c1);
        MMA16816(sacc[nf16 * 2],     ql[0], ql[1], ql[2], ql[3], b0, b1);
        MMA16816(sacc[nf16 * 2 + 1], qh[0], qh[1], qh[2], qh[3], b2, b3);
        MMA16816(sacc[nf16 * 2 + 1], qh[0], qh[1], qh[2], qh[3], c2, c3);
        MMA16816(sacc[nf16 * 2 + 1], ql[0], ql[1], ql[2], ql[3], b2, b3);
      }
    }

    const bool diag = (kt >= 2 * qt);
    float mx0 = -1e30f, mx1 = -1e30f;
#pragma unroll
    for (int nf = 0; nf < 8; nf++) {
      float s0 = sacc[nf][0] * 0.125f, s1 = sacc[nf][1] * 0.125f;
      float s2 = sacc[nf][2] * 0.125f, s3 = sacc[nf][3] * 0.125f;
      if (diag) {
        const int c0 = kt * 64 + nf * 8 + cc2;
        if (c0     > grow0)     s0 = -1e30f;
        if (c0 + 1 > grow0)     s1 = -1e30f;
        if (c0     > grow0 + 8) s2 = -1e30f;
        if (c0 + 1 > grow0 + 8) s3 = -1e30f;
      }
      sacc[nf][0] = s0; sacc[nf][1] = s1; sacc[nf][2] = s2; sacc[nf][3] = s3;
      mx0 = fmaxf(mx0, fmaxf(s0, s1));
      mx1 = fmaxf(mx1, fmaxf(s2, s3));
    }
    mx0 = fmaxf(mx0, __shfl_xor_sync(0xffffffffu, mx0, 1));
    mx0 = fmaxf(mx0, __shfl_xor_sync(0xffffffffu, mx0, 2));
    mx1 = fmaxf(mx1, __shfl_xor_sync(0xffffffffu, mx1, 1));
    mx1 = fmaxf(mx1, __shfl_xor_sync(0xffffffffu, mx1, 2));
    const float m0n = fmaxf(m0, mx0), m1n = fmaxf(m1, mx1);
    const float corr0 = __expf(m0 - m0n), corr1 = __expf(m1 - m1n);
    float rs0 = 0.f, rs1 = 0.f;
#pragma unroll
    for (int nf = 0; nf < 8; nf++) {
      float p0 = __expf(sacc[nf][0] - m0n);
      float p1 = __expf(sacc[nf][1] - m0n);
      float p2 = __expf(sacc[nf][2] - m1n);
      float p3 = __expf(sacc[nf][3] - m1n);
      sacc[nf][0] = p0; sacc[nf][1] = p1; sacc[nf][2] = p2; sacc[nf][3] = p3;
      rs0 += p0 + p1; rs1 += p2 + p3;
    }
    rs0 += __shfl_xor_sync(0xffffffffu, rs0, 1);
    rs0 += __shfl_xor_sync(0xffffffffu, rs0, 2);
    rs1 += __shfl_xor_sync(0xffffffffu, rs1, 1);
    rs1 += __shfl_xor_sync(0xffffffffu, rs1, 2);
    m0 = m0n; m1 = m1n;
    l0 = l0 * corr0 + rs0;
    l1 = l1 * corr1 + rs1;
#pragma unroll
    for (int nf = 0; nf < 8; nf++) {
      oacc[nf][0] *= corr0; oacc[nf][1] *= corr0;
      oacc[nf][2] *= corr1; oacc[nf][3] *= corr1;
    }

#pragma unroll
    for (int kg = 0; kg < 4; kg++) {
      uint32_t ah[4], al[4];
      packPhl(sacc[2 * kg][0],     sacc[2 * kg][1],     ah[0], al[0]);
      packPhl(sacc[2 * kg][2],     sacc[2 * kg][3],     ah[1], al[1]);
      packPhl(sacc[2 * kg + 1][0], sacc[2 * kg + 1][1], ah[2], al[2]);
      packPhl(sacc[2 * kg + 1][2], sacc[2 * kg + 1][3], ah[3], al[3]);
#pragma unroll
      for (int nf16 = 0; nf16 < 4; nf16++) {
        const int row = nf16 * 16 + rB;
        const uint32_t bd = sb + 49152 + row * 128 + (((kg * 2 + hiB) ^ (row & 7)) << 4);
        uint32_t b0, b1, b2, b3, c0, c1, c2, c3;
        LDSM4(b0, b1, b2, b3, bd);
        LDSM4(c0, c1, c2, c3, bd + 8192);
        MMA16816(oacc[nf16 * 2],     ah[0], ah[1], ah[2], ah[3], b0, b1);
        MMA16816(oacc[nf16 * 2],     ah[0], ah[1], ah[2], ah[3], c0, c1);
        MMA16816(oacc[nf16 * 2],     al[0], al[1], al[2], al[3], b0, b1);
        MMA16816(oacc[nf16 * 2 + 1], ah[0], ah[1], ah[2], ah[3], b2, b3);
        MMA16816(oacc[nf16 * 2 + 1], ah[0], ah[1], ah[2], ah[3], c2, c3);
        MMA16816(oacc[nf16 * 2 + 1], al[0], al[1], al[2], al[3], b2, b3);
      }
    }
  }

  const float inv0 = 1.f / l0, inv1 = 1.f / l1;
#pragma unroll
  for (int nf = 0; nf < 8; nf++) {
    const int d = h * 64 + nf * 8 + cc2;
    const size_t o0 = (rowb + grow0) * kE + d;
    const size_t o1 = (rowb + grow0 + 8) * kE + d;
    uint32_t hw, lw;
    packPhl(oacc[nf][0] * inv0, oacc[nf][1] * inv0, hw, lw);
    *(uint32_t*)(outP + o0) = hw;
    *(uint32_t*)(outP + PLE + o0) = lw;
    packPhl(oacc[nf][2] * inv1, oacc[nf][3] * inv1, hw, lw);
    *(uint32_t*)(outP + o1) = hw;
    *(uint32_t*)(outP + PLE + o1) = lw;
  }
}

// ---------------- LayerNorm + residual (fp32 + planes) ----------------
__global__ __launch_bounds__(256) void ln_add_kernel(const float* __restrict__ x,
                                                     const float* __restrict__ gamma,
                                                     const float* __restrict__ beta,
                                                     float* __restrict__ h,
                                                     __nv_bfloat16* __restrict__ hP) {
  __shared__ float rs[8], rs2[8];
  const int row = blockIdx.x, tid = threadIdx.x;
  const int c = tid * 4;
  const size_t off = (size_t)row * kE + c;
  float4 xv = *(const float4*)(x + off);
  float s = xv.x + xv.y + xv.z + xv.w;
  float s2 = xv.x*xv.x + xv.y*xv.y + xv.z*xv.z + xv.w*xv.w;
#pragma unroll
  for (int o = 16; o; o >>= 1) {
    s  += __shfl_xor_sync(0xffffffffu, s, o);
    s2 += __shfl_xor_sync(0xffffffffu, s2, o);
  }
  if ((tid & 31) == 0) { rs[tid >> 5] = s; rs2[tid >> 5] = s2; }
  __syncthreads();
  float ts = 0.f, ts2 = 0.f;
#pragma unroll
  for (int i = 0; i < 8; i++) { ts += rs[i]; ts2 += rs2[i]; }
  const float mean = ts * (1.f / kE);
  const float var = ts2 * (1.f / kE) - mean * mean;
  const float rstd = rsqrtf(var + 1e-6f);
  float4 hv = *(const float4*)(h + off);
  float4 gv = *(const float4*)(gamma + c);
  float4 bv = *(const float4*)(beta + c);
  float4 o4;
  o4.x = (xv.x - mean) * rstd * gv.x + bv.x + hv.x;
  o4.y = (xv.y - mean) * rstd * gv.y + bv.y + hv.y;
  o4.z = (xv.z - mean) * rstd * gv.z + bv.z + hv.z;
  o4.w = (xv.w - mean) * rstd * gv.w + bv.w + hv.w;
  *(float4*)(h + off) = o4;
  __nv_bfloat16 h0,h1,h2,h3,l0,l1,l2,l3;
  split2(o4.x,h0,l0); split2(o4.y,h1,l1); split2(o4.z,h2,l2); split2(o4.w,h3,l3);
  uint2 hp; hp.x = packb(h0,h1); hp.y = packb(h2,h3);
  uint2 lp; lp.x = packb(l0,l1); lp.y = packb(l2,l3);
  *(uint2*)(hP + off) = hp;
  *(uint2*)(hP + (size_t)kM * kE + off) = lp;
}

// ---------------- launcher ----------------
extern "C" void kernel_launch(void* const* d_in, const int* in_sizes, int n_in,
                              void* d_out, int out_size) {
  (void)in_sizes; (void)n_in; (void)out_size;
  const void*  x   = d_in[0];
  const float* we  = (const float*)d_in[1];
  const float* pe  = (const float*)d_in[2];
  const float* KQV = (const float*)d_in[3];
  const float* WO  = (const float*)d_in[4];
  const float* Wup = (const float*)d_in[5];
  const float* bup = (const float*)d_in[6];
  const float* Wdn = (const float*)d_in[7];
  const float* bdn = (const float*)d_in[8];
  const float* g1  = (const float*)d_in[9];
  const float* b1  = (const float*)d_in[10];
  const float* g2  = (const float*)d_in[11];
  const float* b2  = (const float*)d_in[12];
  const float* ub  = (const float*)d_in[13];
  float* out = (float*)d_out;

  float *h, *tb;
  __nv_bfloat16 *qkvP, *hP, *attnP, *ffP, *wKQV, *wWO, *wUp, *wDn, *wWE;
  cudaGetSymbolAddress((void**)&h,     g_h);
  cudaGetSymbolAddress((void**)&tb,    g_t);
  cudaGetSymbolAddress((void**)&qkvP,  g_qkvP);
  cudaGetSymbolAddress((void**)&hP,    g_hP);
  cudaGetSymbolAddress((void**)&attnP, g_attnP);
  cudaGetSymbolAddress((void**)&ffP,   g_ffP);
  cudaGetSymbolAddress((void**)&wKQV,  g_wKQV);
  cudaGetSymbolAddress((void**)&wWO,   g_wWO);
  cudaGetSymbolAddress((void**)&wUp,   g_wUp);
  cudaGetSymbolAddress((void**)&wDn,   g_wDn);
  cudaGetSymbolAddress((void**)&wWE,   g_wWE);

  cudaFuncSetAttribute(attn_mma_kernel, cudaFuncAttributeMaxDynamicSharedMemorySize, 64 * 1024);
  cudaFuncSetAttribute(mm_gemm<0,0,1>, cudaFuncAttributeMaxDynamicSharedMemorySize, SMEM_MM);
  cudaFuncSetAttribute(mm_gemm<0,1,0>, cudaFuncAttributeMaxDynamicSharedMemorySize, SMEM_MM);
  cudaFuncSetAttribute(mm_gemm<2,0,1>, cudaFuncAttributeMaxDynamicSharedMemorySize, SMEM_MM);
  cudaFuncSetAttribute(mm_gemm<1,1,0>, cudaFuncAttributeMaxDynamicSharedMemorySize, SMEM_MM);

  detect_x_kernel<<<1, 32>>>((const int*)x);
  embed_kernel<<<kM, 256>>>(x, we, pe);

  wsplitT_kernel<<<dim3(k3E/32, kE/32, kL), 256>>>(KQV, wKQV, kE, k3E);
  wsplitT_kernel<<<dim3(kE/32,  kE/32, kL), 256>>>(WO,  wWO,  kE, kE);
  wsplitT_kernel<<<dim3(kF/32,  kE/32, kL), 256>>>(Wup, wUp,  kE, kF);
  wsplitT_kernel<<<dim3(kE/32,  kF/32, kL), 256>>>(Wdn, wDn,  kF, kE);
  wsplit_kernel<<<(unsigned)(((size_t)kV*kE/4 + 255)/256), 256>>>(we, wWE, (size_t)kV*kE);

  for (int l = 0; l < kL; l++) {
    mm_gemm<0,0,1><<<dim3(kM/128, k3E/128), 256, SMEM_MM>>>(
        hP, wKQV + (size_t)l*2*k3E*kE, nullptr, nullptr, qkvP, kM, k3E, kE);
    attn_mma_kernel<<<dim3(kS/128, kH, kB), 256, 64*1024>>>(qkvP, attnP);
    mm_gemm<0,1,0><<<dim3(kM/128, kE/128), 256, SMEM_MM>>>(
        attnP, wWO + (size_t)l*2*kE*kE, nullptr, tb, nullptr, kM, kE, kE);
    ln_add_kernel<<<kM, 256>>>(tb, g1 + l*kE, b1 + l*kE, h, hP);
    mm_gemm<2,0,1><<<dim3(kM/128, kF/128), 256, SMEM_MM>>>(
        hP, wUp + (size_t)l*2*kF*kE, bup + (size_t)l*kF, nullptr, ffP, kM, kF, kE);
    mm_gemm<1,1,0><<<dim3(kM/128, kE/128), 256, SMEM_MM>>>(
        ffP, wDn + (size_t)l*2*kE*kF, bdn + (size_t)l*kE, tb, nullptr, kM, kE, kF);
    ln_add_kernel<<<kM, 256>>>(tb, g2 + l*kE, b2 + l*kE, h, hP);
  }

  mm_gemm<1,1,0><<<dim3(kM/128, kV/128), 256, SMEM_MM>>>(
      hP, wWE, ub, out, nullptr, kM, kV, kE);
}